// round 10
// baseline (speedup 1.0000x reference)
#include <cuda_runtime.h>
#include <cuda_bf16.h>

// Per-species linear (X[n,64] . W[species[n],64,1]) + segment_sum over sorted
// structural_indices -> out[n_structures].
// R9: grid-granularity sweep continues (444->2368 blocks monotonically raised
// HBM 6369->6503 GB/s). 8-atom mainloop (51 regs, 5 CTAs/SM resident),
// grid 4736 (~6.4 waves, ~53 atoms/warp) with balanced chunk distribution.
// Traffic is irreducible (528 MB); dur == 528MB / achieved-BW, so the only
// lever is smoothing end-of-kernel imbalance to raise achieved BW.

#define WARPS_PER_BLOCK 8
#define THREADS_PER_BLOCK (WARPS_PER_BLOCK * 32)
#define N_SPECIES 8
#define D_VEC4 16   // 64 floats / 4

__global__ __launch_bounds__(THREADS_PER_BLOCK)
void atomistic_kernel(const float4* __restrict__ X4,
                      const float*  __restrict__ W,
                      const int*    __restrict__ species,
                      const int*    __restrict__ struct_idx,
                      float*        __restrict__ out,
                      int n_atoms,
                      int chunks_base,   // 8-atom chunks per warp (floor)
                      int chunks_rem)    // first chunks_rem warps get one extra
{
    __shared__ float4 Wsh[N_SPECIES * D_VEC4];
    for (int i = threadIdx.x; i < N_SPECIES * D_VEC4; i += blockDim.x)
        Wsh[i] = reinterpret_cast<const float4*>(W)[i];
    __syncthreads();

    const int warp = blockIdx.x * WARPS_PER_BLOCK + (threadIdx.x >> 5);
    const int lane = threadIdx.x & 31;
    const int half = lane >> 4;                  // which 4-atom group of the batch
    const int sub  = lane & 15;                  // float4 column within the row
    const unsigned halfmask = 0xFFFFu << (half * 16);

    // Balanced distribution in units of 8-atom chunks (keeps the int4
    // key/species loads 16B-aligned: every warp start is a multiple of 8).
    const int  my_chunks  = chunks_base + (warp < chunks_rem);
    const long long start = 8LL * ((long long)warp * chunks_base +
                                   (warp < chunks_rem ? warp : chunks_rem));
    long long end = start + 8LL * my_chunks;
    if (end > n_atoms) end = (long long)n_atoms;
    if (start >= end) return;                    // uniform per warp

    const long long n      = end - start;
    const long long nbatch = n >> 3;             // batches of 8 atoms

    int   cur_key = -1;
    float acc0 = 0.0f, acc1 = 0.0f;

    // Flush the current segment for this half-warp (call half-converged).
    auto flush = [&]() {
        float t = acc0 + acc1;
        t += __shfl_xor_sync(halfmask, t, 8);
        t += __shfl_xor_sync(halfmask, t, 4);
        t += __shfl_xor_sync(halfmask, t, 2);
        t += __shfl_xor_sync(halfmask, t, 1);
        if (sub == 0 && cur_key >= 0)
            atomicAdd(out + cur_key, t);
    };
    // Process one atom with boundary check (slow path / tail).
    auto proc1 = [&](int k, int s, float4 x) {
        if (k != cur_key) {
            flush();
            cur_key = k; acc0 = 0.0f; acc1 = 0.0f;
        }
        const float4 w = Wsh[s * D_VEC4 + sub];
        acc0 = fmaf(x.x, w.x, acc0);
        acc1 = fmaf(x.y, w.y, acc1);
        acc0 = fmaf(x.z, w.z, acc0);
        acc1 = fmaf(x.w, w.w, acc1);
    };
    // One fully-loaded atom on the fast path.
    auto fma4 = [&](int s, const float4& x) {
        const float4 w = Wsh[s * D_VEC4 + sub];
        acc0 = fmaf(x.x, w.x, acc0);
        acc1 = fmaf(x.y, w.y, acc1);
        acc0 = fmaf(x.z, w.z, acc0);
        acc1 = fmaf(x.w, w.w, acc1);
    };

    // Hot-loop pointers (this half's first atom is start + half*4).
    const long long a0 = start + half * 4;
    const float4* xp = X4 + a0 * D_VEC4 + sub;
    const int*    kp = struct_idx + a0;
    const int*    sp = species + a0;

    for (long long b = 0; b < nbatch; ++b) {
        // Front-batched loads: 4 independent streaming float4s + vector keys.
        const float4 x0 = __ldcs(xp);
        const float4 x1 = __ldcs(xp + 1 * D_VEC4);
        const float4 x2 = __ldcs(xp + 2 * D_VEC4);
        const float4 x3 = __ldcs(xp + 3 * D_VEC4);
        const int4 kv = *reinterpret_cast<const int4*>(kp);
        const int4 sv = *reinterpret_cast<const int4*>(sp);
        xp += 8 * D_VEC4;   // 8 atoms forward (both halves)
        kp += 8;
        sp += 8;

        if (kv.x == cur_key && kv.w == cur_key) {
            // Sorted keys + first==last==cur -> all 4 atoms in current segment.
            fma4(sv.x, x0); fma4(sv.y, x1); fma4(sv.z, x2); fma4(sv.w, x3);
        } else {
            proc1(kv.x, sv.x, x0);
            proc1(kv.y, sv.y, x1);
            proc1(kv.z, sv.z, x2);
            proc1(kv.w, sv.w, x3);
        }
    }

    // Tail (< 8 atoms): 2 atoms per step, halves interleave; keys stay
    // monotone per half.
    for (long long a = start + nbatch * 8 + half; a < end; a += 2) {
        const int k = struct_idx[a];
        const int s = species[a];
        const float4 x = __ldcs(&X4[a * D_VEC4 + sub]);
        proc1(k, s, x);
    }

    // Final flush (all lanes converged here).
    flush();
}

extern "C" void kernel_launch(void* const* d_in, const int* in_sizes, int n_in,
                              void* d_out, int out_size)
{
    // Input order: X, W, central_species, structural_indices, n_structures
    const float* X  = (const float*)d_in[0];
    const float* W  = (const float*)d_in[1];
    const int*   sp = (const int*)  d_in[2];
    const int*   si = (const int*)  d_in[3];
    float* out = (float*)d_out;

    const int n_atoms = in_sizes[2];

    cudaMemsetAsync(d_out, 0, (size_t)out_size * sizeof(float), 0);

    // Finer oversubscription: ~6.4 waves at 5 CTAs/SM residency.
    // ~53 atoms/warp smooths the end-of-kernel ragged edge further.
    const int blocks = 4736;
    const int total_warps = blocks * WARPS_PER_BLOCK;   // 37888

    // Balanced distribution of 8-atom chunks across warps.
    const int total_chunks = (n_atoms + 7) >> 3;        // 250000 for 2M atoms
    const int chunks_base  = total_chunks / total_warps;
    const int chunks_rem   = total_chunks % total_warps;

    atomistic_kernel<<<blocks, THREADS_PER_BLOCK>>>(
        (const float4*)X, W, sp, si, out, n_atoms, chunks_base, chunks_rem);
}

// round 13
// speedup vs baseline: 1.0294x; 1.0294x over previous
#include <cuda_runtime.h>
#include <cuda_bf16.h>

// Per-species linear (X[n,64] . W[species[n],64,1]) + segment_sum over sorted
// structural_indices -> out[n_structures].
// R10: best empirical config (R8: grid 2368, 8-atom batches, balanced chunks,
// ~3.2 waves @ 5 CTAs/SM) + all-int32 indexing (n_atoms=2M, every index fits
// 31 bits) to cut IMAD.WIDE chains (alu 15.3% -> ~9%). We are at the achieved
// HBM roofline (~6.6 TB/s on this pattern); this shaves the last issue slack.

#define WARPS_PER_BLOCK 8
#define THREADS_PER_BLOCK (WARPS_PER_BLOCK * 32)
#define N_SPECIES 8
#define D_VEC4 16   // 64 floats / 4

__global__ __launch_bounds__(THREADS_PER_BLOCK)
void atomistic_kernel(const float4* __restrict__ X4,
                      const float*  __restrict__ W,
                      const int*    __restrict__ species,
                      const int*    __restrict__ struct_idx,
                      float*        __restrict__ out,
                      int n_atoms,
                      int chunks_base,   // 8-atom chunks per warp (floor)
                      int chunks_rem)    // first chunks_rem warps get one extra
{
    __shared__ float4 Wsh[N_SPECIES * D_VEC4];
    for (int i = threadIdx.x; i < N_SPECIES * D_VEC4; i += blockDim.x)
        Wsh[i] = reinterpret_cast<const float4*>(W)[i];
    __syncthreads();

    const int warp = blockIdx.x * WARPS_PER_BLOCK + (threadIdx.x >> 5);
    const int lane = threadIdx.x & 31;
    const int half = lane >> 4;                  // which 4-atom group of the batch
    const int sub  = lane & 15;                  // float4 column within the row
    const unsigned halfmask = 0xFFFFu << (half * 16);

    // Balanced distribution in units of 8-atom chunks (keeps the int4
    // key/species loads 16B-aligned). All arithmetic fits in int32:
    // n_atoms = 2e6, max element index 2e6*16 = 3.2e7 << 2^31.
    const int my_chunks = chunks_base + (warp < chunks_rem);
    const int start = 8 * (warp * chunks_base +
                           (warp < chunks_rem ? warp : chunks_rem));
    int end = start + 8 * my_chunks;
    if (end > n_atoms) end = n_atoms;
    if (start >= end) return;                    // uniform per warp

    const int nbatch = (end - start) >> 3;       // batches of 8 atoms

    int   cur_key = -1;
    float acc0 = 0.0f, acc1 = 0.0f;

    // Flush the current segment for this half-warp (call half-converged).
    auto flush = [&]() {
        float t = acc0 + acc1;
        t += __shfl_xor_sync(halfmask, t, 8);
        t += __shfl_xor_sync(halfmask, t, 4);
        t += __shfl_xor_sync(halfmask, t, 2);
        t += __shfl_xor_sync(halfmask, t, 1);
        if (sub == 0 && cur_key >= 0)
            atomicAdd(out + cur_key, t);
    };
    // Process one atom with boundary check (slow path / tail).
    auto proc1 = [&](int k, int s, float4 x) {
        if (k != cur_key) {
            flush();
            cur_key = k; acc0 = 0.0f; acc1 = 0.0f;
        }
        const float4 w = Wsh[s * D_VEC4 + sub];
        acc0 = fmaf(x.x, w.x, acc0);
        acc1 = fmaf(x.y, w.y, acc1);
        acc0 = fmaf(x.z, w.z, acc0);
        acc1 = fmaf(x.w, w.w, acc1);
    };
    // One fully-loaded atom on the fast path.
    auto fma4 = [&](int s, const float4& x) {
        const float4 w = Wsh[s * D_VEC4 + sub];
        acc0 = fmaf(x.x, w.x, acc0);
        acc1 = fmaf(x.y, w.y, acc1);
        acc0 = fmaf(x.z, w.z, acc0);
        acc1 = fmaf(x.w, w.w, acc1);
    };

    // Hot-loop pointers (this half's first atom is start + half*4).
    const int a0 = start + half * 4;
    const float4* xp = X4 + (size_t)a0 * D_VEC4 + sub;
    const int*    kp = struct_idx + a0;
    const int*    sp = species + a0;

    for (int b = 0; b < nbatch; ++b) {
        // Front-batched loads: 4 independent streaming float4s + vector keys.
        const float4 x0 = __ldcs(xp);
        const float4 x1 = __ldcs(xp + 1 * D_VEC4);
        const float4 x2 = __ldcs(xp + 2 * D_VEC4);
        const float4 x3 = __ldcs(xp + 3 * D_VEC4);
        const int4 kv = *reinterpret_cast<const int4*>(kp);
        const int4 sv = *reinterpret_cast<const int4*>(sp);
        xp += 8 * D_VEC4;   // 8 atoms forward (both halves)
        kp += 8;
        sp += 8;

        if (kv.x == cur_key && kv.w == cur_key) {
            // Sorted keys + first==last==cur -> all 4 atoms in current segment.
            fma4(sv.x, x0); fma4(sv.y, x1); fma4(sv.z, x2); fma4(sv.w, x3);
        } else {
            proc1(kv.x, sv.x, x0);
            proc1(kv.y, sv.y, x1);
            proc1(kv.z, sv.z, x2);
            proc1(kv.w, sv.w, x3);
        }
    }

    // Tail (< 8 atoms): 2 atoms per step, halves interleave; keys stay
    // monotone per half.
    for (int a = start + nbatch * 8 + half; a < end; a += 2) {
        const int k = struct_idx[a];
        const int s = species[a];
        const float4 x = __ldcs(&X4[(size_t)a * D_VEC4 + sub]);
        proc1(k, s, x);
    }

    // Final flush (all lanes converged here).
    flush();
}

extern "C" void kernel_launch(void* const* d_in, const int* in_sizes, int n_in,
                              void* d_out, int out_size)
{
    // Input order: X, W, central_species, structural_indices, n_structures
    const float* X  = (const float*)d_in[0];
    const float* W  = (const float*)d_in[1];
    const int*   sp = (const int*)  d_in[2];
    const int*   si = (const int*)  d_in[3];
    float* out = (float*)d_out;

    const int n_atoms = in_sizes[2];

    cudaMemsetAsync(d_out, 0, (size_t)out_size * sizeof(float), 0);

    // Best measured config: ~3.2 waves at 5 CTAs/SM residency, ~106 atoms/warp.
    const int blocks = 2368;
    const int total_warps = blocks * WARPS_PER_BLOCK;   // 18944

    // Balanced distribution of 8-atom chunks across warps.
    const int total_chunks = (n_atoms + 7) >> 3;        // 250000 for 2M atoms
    const int chunks_base  = total_chunks / total_warps;
    const int chunks_rem   = total_chunks % total_warps;

    atomistic_kernel<<<blocks, THREADS_PER_BLOCK>>>(
        (const float4*)X, W, sp, si, out, n_atoms, chunks_base, chunks_rem);
}